// round 13
// baseline (speedup 1.0000x reference)
#include <cuda_runtime.h>
#include <cstdint>

// NonLocalMeansSmoothing: x [8,256,256,8] fp32 -> same. K=5, sigma=1, h=1.
// w ∝ exp(-(||c-n||^2 + 0.5*(di^2+dj^2)))  (gaussian global norm cancels)
// ||c-n||^2 = ||c||^2 + ||n||^2 - 2 c·n, norms pre-scaled by -log2e in smem.
//
// R12: combine R3's low smem traffic (2 vertical px/thread, 540 B/px) with
// R11's occupancy lever: 256-thr CTAs, __launch_bounds__(256,5) -> 51-reg
// cap, 40 warps/SM (vs R3's 32). Tree-shaped packed dot keeps live state
// minimal to fit the cap.

#define BATCH 8
#define NX 256
#define NY 256
#define TILEX 32            // columns (ny)
#define TILEY 16            // rows (nx)
#define HALO 2
#define SMX (TILEX + 2 * HALO)   // 36
#define SMY (TILEY + 2 * HALO)   // 20
#define L2E 1.4426950408889634f

typedef unsigned long long u64;

__device__ __forceinline__ u64 fma2(u64 a, u64 b, u64 c) {
    u64 d; asm("fma.rn.f32x2 %0,%1,%2,%3;" : "=l"(d) : "l"(a), "l"(b), "l"(c)); return d;
}
__device__ __forceinline__ u64 mul2(u64 a, u64 b) {
    u64 d; asm("mul.rn.f32x2 %0,%1,%2;" : "=l"(d) : "l"(a), "l"(b)); return d;
}
__device__ __forceinline__ u64 add2(u64 a, u64 b) {
    u64 d; asm("add.rn.f32x2 %0,%1,%2;" : "=l"(d) : "l"(a), "l"(b)); return d;
}
__device__ __forceinline__ u64 pack2(float lo, float hi) {
    u64 d; asm("mov.b64 %0,{%1,%2};" : "=l"(d) : "f"(lo), "f"(hi)); return d;
}
__device__ __forceinline__ float hadd2(u64 a) {
    float lo, hi; asm("mov.b64 {%0,%1},%2;" : "=f"(lo), "=f"(hi) : "l"(a));
    return lo + hi;
}
__device__ __forceinline__ float ex2f(float x) {
    float r; asm("ex2.approx.ftz.f32 %0,%1;" : "=f"(r) : "f"(x)); return r;
}
__device__ __forceinline__ int refl(int p, int n) {
    if (p < 0) p = -p;
    if (p >= n) p = 2 * n - 2 - p;
    return p;
}

__global__ __launch_bounds__(256, 5)
void nlm_kernel(const float* __restrict__ x, float* __restrict__ out) {
    __shared__ ulonglong2 sm0[SMY][SMX];   // ch 0-3
    __shared__ ulonglong2 sm1[SMY][SMX];   // ch 4-7
    __shared__ float      snl[SMY][SMX];   // -log2e * ||v||^2

    const int b   = blockIdx.z;
    const int ti0 = blockIdx.y * TILEY;
    const int tj0 = blockIdx.x * TILEX;
    const int tid = threadIdx.y * 32 + threadIdx.x;

    const float* xb = x + (size_t)b * NX * NY * 8;

    // Halo load: 720 sites / 256 threads.
    for (int p = tid; p < SMY * SMX; p += 256) {
        int r = p / SMX;
        int c = p - r * SMX;
        int gi = refl(ti0 + r - HALO, NX);
        int gj = refl(tj0 + c - HALO, NY);
        const float4* src = reinterpret_cast<const float4*>(
            xb + ((size_t)gi * NY + gj) * 8);
        float4 v0 = src[0];
        float4 v1 = src[1];
        *reinterpret_cast<float4*>(&sm0[r][c]) = v0;
        *reinterpret_cast<float4*>(&sm1[r][c]) = v1;
        float nrm = v0.x * v0.x + v0.y * v0.y + v0.z * v0.z + v0.w * v0.w
                  + v1.x * v1.x + v1.y * v1.y + v1.z * v1.z + v1.w * v1.w;
        snl[r][c] = -L2E * nrm;
    }
    __syncthreads();

    // Two vertically adjacent pixels per thread (8 y-threads x 2 = 16 rows).
    const int y0  = 2 * threadIdx.y;           // tile-local row of pixel0
    const int li0 = y0 + HALO;
    const int lj  = threadIdx.x + HALO;

    const ulonglong2 C00 = sm0[li0][lj];
    const ulonglong2 C01 = sm1[li0][lj];
    const float      pc0 = snl[li0][lj];
    const ulonglong2 C10 = sm0[li0 + 1][lj];
    const ulonglong2 C11 = sm1[li0 + 1][lj];
    const float      pc1 = snl[li0 + 1][lj];

    u64 p0a = 0, p0b = 0, p0c = 0, p0d = 0;
    u64 p1a = 0, p1b = 0, p1c = 0, p1d = 0;
    float ws0 = 0.f, ws1 = 0.f;

    // Window rows r = 0..5 map to smem rows y0 + r.
    // pixel0 uses r in [0,4] (di = r-2); pixel1 uses r in [1,5] (di = r-3).
#pragma unroll
    for (int r = 0; r < 6; r++) {
#pragma unroll
        for (int dj = -HALO; dj <= HALO; dj++) {
            const int sr = y0 + r;
            const ulonglong2 N0 = sm0[sr][lj + dj];
            const ulonglong2 N1 = sm1[sr][lj + dj];
            const float ns = snl[sr][lj + dj];

            if (r <= 4) {
                const int di = r - 2;
                const float cg = -L2E * (0.5f * (float)(di * di + dj * dj));
                u64 dp1 = mul2(C00.x, N0.x);
                u64 dp2 = mul2(C00.y, N0.y);
                dp1 = fma2(C01.x, N1.x, dp1);
                dp2 = fma2(C01.y, N1.y, dp2);
                const float e = fmaf(2.0f * L2E, hadd2(add2(dp1, dp2)),
                                     pc0 + (ns + cg));
                const float w = ex2f(e);
                const u64 w2 = pack2(w, w);
                p0a = fma2(w2, N0.x, p0a);
                p0b = fma2(w2, N0.y, p0b);
                p0c = fma2(w2, N1.x, p0c);
                p0d = fma2(w2, N1.y, p0d);
                ws0 += w;
            }
            if (r >= 1) {
                const int di = r - 3;
                const float cg = -L2E * (0.5f * (float)(di * di + dj * dj));
                u64 dp1 = mul2(C10.x, N0.x);
                u64 dp2 = mul2(C10.y, N0.y);
                dp1 = fma2(C11.x, N1.x, dp1);
                dp2 = fma2(C11.y, N1.y, dp2);
                const float e = fmaf(2.0f * L2E, hadd2(add2(dp1, dp2)),
                                     pc1 + (ns + cg));
                const float w = ex2f(e);
                const u64 w2 = pack2(w, w);
                p1a = fma2(w2, N0.x, p1a);
                p1b = fma2(w2, N0.y, p1b);
                p1c = fma2(w2, N1.x, p1c);
                p1d = fma2(w2, N1.y, p1d);
                ws1 += w;
            }
        }
    }

    const int gi0 = ti0 + y0;
    const int gj  = tj0 + threadIdx.x;

    {
        const float inv = __fdividef(1.f, ws0);
        const u64 inv2 = pack2(inv, inv);
        ulonglong2 r0, r1;
        r0.x = mul2(p0a, inv2); r0.y = mul2(p0b, inv2);
        r1.x = mul2(p0c, inv2); r1.y = mul2(p0d, inv2);
        ulonglong2* dst = reinterpret_cast<ulonglong2*>(
            out + (((size_t)b * NX + gi0) * NY + gj) * 8);
        dst[0] = r0; dst[1] = r1;
    }
    {
        const float inv = __fdividef(1.f, ws1);
        const u64 inv2 = pack2(inv, inv);
        ulonglong2 r0, r1;
        r0.x = mul2(p1a, inv2); r0.y = mul2(p1b, inv2);
        r1.x = mul2(p1c, inv2); r1.y = mul2(p1d, inv2);
        ulonglong2* dst = reinterpret_cast<ulonglong2*>(
            out + (((size_t)b * NX + gi0 + 1) * NY + gj) * 8);
        dst[0] = r0; dst[1] = r1;
    }
}

extern "C" void kernel_launch(void* const* d_in, const int* in_sizes, int n_in,
                              void* d_out, int out_size) {
    const float* x = (const float*)d_in[0];
    float* out = (float*)d_out;
    dim3 block(32, 8, 1);
    dim3 grid(NY / TILEX, NX / TILEY, BATCH);  // (8, 16, 8) = 1024 CTAs
    nlm_kernel<<<grid, block>>>(x, out);
}

// round 14
// speedup vs baseline: 2.1863x; 2.1863x over previous
#include <cuda_runtime.h>
#include <cstdint>

// NonLocalMeansSmoothing: x [8,256,256,8] fp32 -> same. K=5, sigma=1, h=1.
// w ∝ exp(-(||c-n||^2 + 0.5*(di^2+dj^2)))  (gaussian global norm cancels)
//
// R14: R11's high-occupancy shape (1 px/thread, 512-thr CTA, 3 CTAs/SM,
// 48 warps/SM, 42-reg cap) + DIRECT packed-difference distance: no norm
// plane in smem -> 2 LDS.128 per tap instead of 2xLDS.128+LDS.32
// (33% fewer LDS issues, 900->800 B/px crossbar traffic) and fewer live
// registers. Distance via sub2/fma2 tree, exp via ex2.

#define BATCH 8
#define NX 256
#define NY 256
#define TILEX 32            // columns (ny)
#define TILEY 16            // rows (nx)
#define HALO 2
#define SMX (TILEX + 2 * HALO)   // 36
#define SMY (TILEY + 2 * HALO)   // 20
#define L2E 1.4426950408889634f

typedef unsigned long long u64;

__device__ __forceinline__ u64 fma2(u64 a, u64 b, u64 c) {
    u64 d; asm("fma.rn.f32x2 %0,%1,%2,%3;" : "=l"(d) : "l"(a), "l"(b), "l"(c)); return d;
}
__device__ __forceinline__ u64 mul2(u64 a, u64 b) {
    u64 d; asm("mul.rn.f32x2 %0,%1,%2;" : "=l"(d) : "l"(a), "l"(b)); return d;
}
__device__ __forceinline__ u64 sub2(u64 a, u64 b) {
    u64 d; asm("sub.rn.f32x2 %0,%1,%2;" : "=l"(d) : "l"(a), "l"(b)); return d;
}
__device__ __forceinline__ u64 add2(u64 a, u64 b) {
    u64 d; asm("add.rn.f32x2 %0,%1,%2;" : "=l"(d) : "l"(a), "l"(b)); return d;
}
__device__ __forceinline__ u64 pack2(float lo, float hi) {
    u64 d; asm("mov.b64 %0,{%1,%2};" : "=l"(d) : "f"(lo), "f"(hi)); return d;
}
__device__ __forceinline__ float hadd2(u64 a) {
    float lo, hi; asm("mov.b64 {%0,%1},%2;" : "=f"(lo), "=f"(hi) : "l"(a));
    return lo + hi;
}
__device__ __forceinline__ float ex2f(float x) {
    float r; asm("ex2.approx.ftz.f32 %0,%1;" : "=f"(r) : "f"(x)); return r;
}
__device__ __forceinline__ int refl(int p, int n) {
    if (p < 0) p = -p;
    if (p >= n) p = 2 * n - 2 - p;
    return p;
}

__global__ __launch_bounds__(512, 3)
void nlm_kernel(const float* __restrict__ x, float* __restrict__ out) {
    __shared__ ulonglong2 sm0[SMY][SMX];   // ch 0-3
    __shared__ ulonglong2 sm1[SMY][SMX];   // ch 4-7

    const int b   = blockIdx.z;
    const int ti0 = blockIdx.y * TILEY;
    const int tj0 = blockIdx.x * TILEX;
    const int tid = threadIdx.y * 32 + threadIdx.x;

    const float* xb = x + (size_t)b * NX * NY * 8;

    // Halo load: 720 sites / 512 threads.
    for (int p = tid; p < SMY * SMX; p += 512) {
        int r = p / SMX;
        int c = p - r * SMX;
        int gi = refl(ti0 + r - HALO, NX);
        int gj = refl(tj0 + c - HALO, NY);
        const float4* src = reinterpret_cast<const float4*>(
            xb + ((size_t)gi * NY + gj) * 8);
        *reinterpret_cast<float4*>(&sm0[r][c]) = src[0];
        *reinterpret_cast<float4*>(&sm1[r][c]) = src[1];
    }
    __syncthreads();

    const int li = threadIdx.y + HALO;
    const int lj = threadIdx.x + HALO;

    const ulonglong2 C0 = sm0[li][lj];
    const ulonglong2 C1 = sm1[li][lj];

    u64 a0 = 0, a1 = 0, a2 = 0, a3 = 0;
    float wsum = 0.f;

#pragma unroll
    for (int di = -HALO; di <= HALO; di++) {
#pragma unroll
        for (int dj = -HALO; dj <= HALO; dj++) {
            const ulonglong2 N0 = sm0[li + di][lj + dj];
            const ulonglong2 N1 = sm1[li + di][lj + dj];

            // ||c-n||^2 via packed differences, tree-shaped.
            u64 t0 = sub2(C0.x, N0.x);
            u64 t1 = sub2(C0.y, N0.y);
            u64 t2 = sub2(C1.x, N1.x);
            u64 t3 = sub2(C1.y, N1.y);
            u64 d1 = mul2(t0, t0);
            u64 d2 = mul2(t1, t1);
            d1 = fma2(t2, t2, d1);
            d2 = fma2(t3, t3, d2);
            const float d = hadd2(add2(d1, d2));

            const float cg = -L2E * (0.5f * (float)(di * di + dj * dj));
            const float w = ex2f(fmaf(-L2E, d, cg));
            const u64 w2 = pack2(w, w);
            a0 = fma2(w2, N0.x, a0);
            a1 = fma2(w2, N0.y, a1);
            a2 = fma2(w2, N1.x, a2);
            a3 = fma2(w2, N1.y, a3);
            wsum += w;
        }
    }

    const float inv = __fdividef(1.f, wsum);
    const u64 inv2 = pack2(inv, inv);
    ulonglong2 r0, r1;
    r0.x = mul2(a0, inv2); r0.y = mul2(a1, inv2);
    r1.x = mul2(a2, inv2); r1.y = mul2(a3, inv2);

    const int gi = ti0 + threadIdx.y;
    const int gj = tj0 + threadIdx.x;
    ulonglong2* dst = reinterpret_cast<ulonglong2*>(
        out + (((size_t)b * NX + gi) * NY + gj) * 8);
    dst[0] = r0;
    dst[1] = r1;
}

extern "C" void kernel_launch(void* const* d_in, const int* in_sizes, int n_in,
                              void* d_out, int out_size) {
    const float* x = (const float*)d_in[0];
    float* out = (float*)d_out;
    dim3 block(32, 16, 1);
    dim3 grid(NY / TILEX, NX / TILEY, BATCH);  // (8, 16, 8) = 1024 CTAs
    nlm_kernel<<<grid, block>>>(x, out);
}